// round 4
// baseline (speedup 1.0000x reference)
#include <cuda_runtime.h>
#include <math.h>

#define N_NODES 50000
#define N_EDGES 600000
#define N_GRAPHS 64
#define HID 128
#define IN_DIM 16
#define OUT_DIM 256
#define N_LAYERS 3
#define STRIDE 132   // padded row stride (floats) for smem X tiles

typedef unsigned long long ull;

// ---------------- device scratch (static, no allocation) ----------------
__device__ float d_h[N_NODES * HID];
__device__ float d_A[N_NODES * HID];     // h@W1a + b1   (also reused for emb_out result)
__device__ float d_B[N_NODES * HID];     // h@W1b
__device__ float d_T[N_NODES * HID];     // node-update hidden
__device__ float d_magg[N_NODES * HID];  // edge message aggregation
__device__ float d_cagg[N_NODES * 3];
__device__ float d_coord[N_NODES * 3];
__device__ float d_deg[N_NODES];
__device__ float d_gsum[N_GRAPHS * HID];
__device__ float d_gcnt[N_GRAPHS];

__device__ __forceinline__ float silu_f(float x) {
    return x / (1.0f + __expf(-x));
}

// packed f32x2 fma: d += a * b (lane-wise on two packed fp32).
// Falls back to two scalar FMAs on toolkits without PTX ISA 8.6.
__device__ __forceinline__ void fma2(ull& d, ull a, ull b) {
#if defined(CUDART_VERSION) && (CUDART_VERSION >= 12080)
    asm("fma.rn.f32x2 %0, %1, %2, %0;" : "+l"(d) : "l"(a), "l"(b));
#else
    float2 df, af, bf;
    df.x = __uint_as_float((unsigned)(d & 0xffffffffull));
    df.y = __uint_as_float((unsigned)(d >> 32));
    af.x = __uint_as_float((unsigned)(a & 0xffffffffull));
    af.y = __uint_as_float((unsigned)(a >> 32));
    bf.x = __uint_as_float((unsigned)(b & 0xffffffffull));
    bf.y = __uint_as_float((unsigned)(b >> 32));
    df.x = fmaf(af.x, bf.x, df.x);
    df.y = fmaf(af.y, bf.y, df.y);
    d = ((ull)__float_as_uint(df.y) << 32) | (ull)__float_as_uint(df.x);
#endif
}
__device__ __forceinline__ float sum2(ull v) {
    float2 f;
    f.x = __uint_as_float((unsigned)(v & 0xffffffffull));
    f.y = __uint_as_float((unsigned)(v >> 32));
    return f.x + f.y;
}

// ---------------- init ----------------
__global__ void init_kernel(const float* __restrict__ coord_in) {
    int idx = blockIdx.x * blockDim.x + threadIdx.x;
    if (idx < N_NODES * HID) d_magg[idx] = 0.0f;
    if (idx < N_NODES * 3) { d_cagg[idx] = 0.0f; d_coord[idx] = coord_in[idx]; }
    if (idx < N_NODES) d_deg[idx] = 0.0f;
    if (idx < N_GRAPHS * HID) d_gsum[idx] = 0.0f;
    if (idx < N_GRAPHS) d_gcnt[idx] = 0.0f;
}

__global__ void deg_kernel(const int* __restrict__ row) {
    int e = blockIdx.x * blockDim.x + threadIdx.x;
    if (e < N_EDGES) atomicAdd(&d_deg[row[e]], 1.0f);
}

// ---------------- embedding in: h = x @ W + b  (K=16) ----------------
__global__ void emb_in_kernel(const float* __restrict__ x,
                              const float* __restrict__ w,
                              const float* __restrict__ b) {
    int idx = blockIdx.x * blockDim.x + threadIdx.x;
    if (idx >= N_NODES * HID) return;
    int n = idx >> 7, ch = idx & 127;
    float acc = b[ch];
#pragma unroll
    for (int k = 0; k < IN_DIM; k++) acc += x[n * IN_DIM + k] * w[k * HID + ch];
    d_h[idx] = acc;
}

// ---------------- weight repack: global row-major [128][128] -> smem [64 k2][128 c][2 parity]
__device__ __forceinline__ void repack_w(const float* __restrict__ W, float* __restrict__ Wp,
                                         int tid, int nthreads) {
    for (int idx = tid; idx < 4096; idx += nthreads) {
        int k = idx >> 5;             // 0..127
        int c0 = (idx & 31) * 4;      // 0..124
        float4 v = reinterpret_cast<const float4*>(W)[idx];
        int k2 = k >> 1, p = k & 1;
        float* dst = &Wp[k2 * 256 + p];
        dst[(c0 + 0) * 2] = v.x;
        dst[(c0 + 1) * 2] = v.y;
        dst[(c0 + 2) * 2] = v.z;
        dst[(c0 + 3) * 2] = v.w;
    }
}

// ---------------- packed micro GEMM: 4 rows x 8 cols (4 col-pairs) per thread ----------------
// Xs: smem [64][STRIDE] row-major; Wp: packed [64][256]
// thread covers rows row0..row0+3, cols {2*cg+32m, 2*cg+32m+1} m=0..3
__device__ __forceinline__ void mgemm2(const float* __restrict__ Xs,
                                       const float* __restrict__ Wp,
                                       int row0, int cg, ull acc[4][4][2]) {
#pragma unroll
    for (int i = 0; i < 4; i++)
#pragma unroll
        for (int m = 0; m < 4; m++) { acc[i][m][0] = 0ull; acc[i][m][1] = 0ull; }
    const float* xb = Xs + row0 * STRIDE;
#pragma unroll 2
    for (int k2 = 0; k2 < 64; k2++) {
        ull x0 = *reinterpret_cast<const ull*>(xb + 0 * STRIDE + 2 * k2);
        ull x1 = *reinterpret_cast<const ull*>(xb + 1 * STRIDE + 2 * k2);
        ull x2 = *reinterpret_cast<const ull*>(xb + 2 * STRIDE + 2 * k2);
        ull x3 = *reinterpret_cast<const ull*>(xb + 3 * STRIDE + 2 * k2);
        const float* wrow = Wp + k2 * 256 + 4 * cg;
#pragma unroll
        for (int m = 0; m < 4; m++) {
            ulonglong2 wv = *reinterpret_cast<const ulonglong2*>(wrow + 64 * m);
            fma2(acc[0][m][0], x0, wv.x); fma2(acc[0][m][1], x0, wv.y);
            fma2(acc[1][m][0], x1, wv.x); fma2(acc[1][m][1], x1, wv.y);
            fma2(acc[2][m][0], x2, wv.x); fma2(acc[2][m][1], x2, wv.y);
            fma2(acc[3][m][0], x3, wv.x); fma2(acc[3][m][1], x3, wv.y);
        }
    }
}

// ---------------- generic node GEMM: Y = op(X@W (+bias) (+Y)) ----------------
#define GM_BIAS 1
#define GM_ACC 2
#define GM_SILU 4
#define GM_CLEARX 8
__global__ void __launch_bounds__(256, 2)
gemm128_kernel(float* __restrict__ X, const float* __restrict__ W,
               const float* __restrict__ bias, float* __restrict__ Y, int mode) {
    extern __shared__ float sm[];
    float* Wp = sm;                 // 16384 floats (packed)
    float* Xs = sm + 16384;         // 64*STRIDE
    float* bs = Xs + 64 * STRIDE;   // 128
    int tid = threadIdx.x;
    repack_w(W, Wp, tid, 256);
    if (tid < 128) bs[tid] = (mode & GM_BIAS) ? bias[tid] : 0.0f;
    __syncthreads();

    int warp = tid >> 5, tx = tid & 31;
    int rh = tx >> 4, cg = tx & 15;
    int row0 = warp * 8 + rh * 4;

    int ntiles = (N_NODES + 63) / 64;
    for (int tile = blockIdx.x; tile < ntiles; tile += gridDim.x) {
        int r0 = tile * 64;
#pragma unroll
        for (int i = 0; i < 32; i++) {
            int idx = i * 256 + tid;
            int r = idx >> 7, k = idx & 127;
            int gr = r0 + r;
            float v = 0.0f;
            if (gr < N_NODES) {
                v = X[gr * HID + k];
                if (mode & GM_CLEARX) X[gr * HID + k] = 0.0f;
            }
            Xs[r * STRIDE + k] = v;
        }
        __syncthreads();
        ull acc[4][4][2];
        mgemm2(Xs, Wp, row0, cg, acc);
#pragma unroll
        for (int i = 0; i < 4; i++) {
            int gr = r0 + row0 + i;
            if (gr < N_NODES) {
#pragma unroll
                for (int m = 0; m < 4; m++) {
                    int c = 2 * cg + 32 * m;
                    float2 res;
                    res.x = sum2(acc[i][m][0]) + bs[c];
                    res.y = sum2(acc[i][m][1]) + bs[c + 1];
                    float* yp = &Y[gr * HID + c];
                    if (mode & GM_ACC) {
                        float2 o = *reinterpret_cast<float2*>(yp);
                        res.x += o.x; res.y += o.y;
                    }
                    if (mode & GM_SILU) { res.x = silu_f(res.x); res.y = silu_f(res.y); }
                    *reinterpret_cast<float2*>(yp) = res;
                }
            }
        }
        __syncthreads();
    }
}

// ---------------- edge kernel: per-64-edge tile fused edge MLP ----------------
__global__ void __launch_bounds__(256, 1)
edge_kernel(const int* __restrict__ row, const int* __restrict__ col,
            const float* __restrict__ ea,
            const float* __restrict__ W2, const float* __restrict__ b2,
            const float* __restrict__ Wc1, const float* __restrict__ bc1,
            const float* __restrict__ wc2,
            const float* __restrict__ wr, const float* __restrict__ we) {
    extern __shared__ float sm[];
    float* W2p = sm;                    // 16384 (packed)
    float* Wc1p = W2p + 16384;          // 16384 (packed)
    float* tS = Wc1p + 16384;           // 64*STRIDE
    float* mS = tS + 64 * STRIDE;       // 64*STRIDE
    float* b2s = mS + 64 * STRIDE;      // 128
    float* bc1s = b2s + 128;
    float* wc2s = bc1s + 128;
    float* wrs = wc2s + 128;
    float* wes = wrs + 128;
    float* diffs = wes + 128;           // 64*3
    int* rows_s = (int*)(diffs + 192);  // 64

    int tid = threadIdx.x;
    repack_w(W2, W2p, tid, 256);
    repack_w(Wc1, Wc1p, tid, 256);
    if (tid < 128) {
        b2s[tid] = b2[tid]; bc1s[tid] = bc1[tid]; wc2s[tid] = wc2[tid];
        wrs[tid] = wr[tid]; wes[tid] = we[tid];
    }
    __syncthreads();

    int warp = tid >> 5, tx = tid & 31;
    int rh = tx >> 4, cg = tx & 15;
    int row0 = warp * 8 + rh * 4;
    int e_loc = tid >> 2, q = tid & 3;
    int ntiles = (N_EDGES + 63) / 64;

    for (int tile = blockIdx.x; tile < ntiles; tile += gridDim.x) {
        int e0 = tile * 64;
        int e = e0 + e_loc;
        // ---- Phase A: gather pre-activation, silu -> tS ----
        if (e < N_EDGES) {
            int r = row[e], c = col[e];
            float dx = d_coord[r * 3 + 0] - d_coord[c * 3 + 0];
            float dy = d_coord[r * 3 + 1] - d_coord[c * 3 + 1];
            float dz = d_coord[r * 3 + 2] - d_coord[c * 3 + 2];
            float radial = dx * dx + dy * dy + dz * dz;
            float eav = ea[e];
            if (q == 0) {
                rows_s[e_loc] = r;
                diffs[e_loc * 3 + 0] = dx; diffs[e_loc * 3 + 1] = dy; diffs[e_loc * 3 + 2] = dz;
            }
#pragma unroll
            for (int jj = 0; jj < 8; jj++) {
                int ch = q * 32 + jj * 4;
                float4 av = *reinterpret_cast<const float4*>(&d_A[r * HID + ch]);
                float4 bv = *reinterpret_cast<const float4*>(&d_B[c * HID + ch]);
                float4 w1 = *reinterpret_cast<const float4*>(&wrs[ch]);
                float4 w2v = *reinterpret_cast<const float4*>(&wes[ch]);
                float4 tv;
                tv.x = silu_f(av.x + bv.x + radial * w1.x + eav * w2v.x);
                tv.y = silu_f(av.y + bv.y + radial * w1.y + eav * w2v.y);
                tv.z = silu_f(av.z + bv.z + radial * w1.z + eav * w2v.z);
                tv.w = silu_f(av.w + bv.w + radial * w1.w + eav * w2v.w);
                *reinterpret_cast<float4*>(&tS[e_loc * STRIDE + ch]) = tv;
            }
        } else {
#pragma unroll
            for (int jj = 0; jj < 8; jj++) {
                int ch = q * 32 + jj * 4;
                *reinterpret_cast<float4*>(&tS[e_loc * STRIDE + ch]) = make_float4(0.f, 0.f, 0.f, 0.f);
            }
            if (q == 0) rows_s[e_loc] = 0;
        }
        __syncthreads();

        // ---- Phase B: m = silu(t @ W2 + b2) -> mS ----
        {
            ull acc[4][4][2];
            mgemm2(tS, W2p, row0, cg, acc);
#pragma unroll
            for (int i = 0; i < 4; i++) {
#pragma unroll
                for (int m = 0; m < 4; m++) {
                    int c = 2 * cg + 32 * m;
                    float2 mv;
                    mv.x = silu_f(sum2(acc[i][m][0]) + b2s[c]);
                    mv.y = silu_f(sum2(acc[i][m][1]) + b2s[c + 1]);
                    *reinterpret_cast<float2*>(&mS[(row0 + i) * STRIDE + c]) = mv;
                }
            }
        }
        __syncthreads();

        // ---- Phase B2: scatter magg ----
#pragma unroll
        for (int i = 0; i < 32; i++) {
            int idx = i * 256 + tid;
            int el = idx >> 7, ch = idx & 127;
            if (e0 + el < N_EDGES)
                atomicAdd(&d_magg[rows_s[el] * HID + ch], mS[el * STRIDE + ch]);
        }

        // ---- Phase C: cw = silu(m @ Wc1 + bc1) . wc2 ; scatter coord agg ----
        {
            ull acc[4][4][2];
            mgemm2(mS, Wc1p, row0, cg, acc);
            float part[4];
#pragma unroll
            for (int i = 0; i < 4; i++) {
                part[i] = 0.0f;
#pragma unroll
                for (int m = 0; m < 4; m++) {
                    int c = 2 * cg + 32 * m;
                    part[i] += silu_f(sum2(acc[i][m][0]) + bc1s[c]) * wc2s[c];
                    part[i] += silu_f(sum2(acc[i][m][1]) + bc1s[c + 1]) * wc2s[c + 1];
                }
            }
            // reduce across the 16 col-group lanes (stay within each 16-lane half)
#pragma unroll
            for (int off = 8; off > 0; off >>= 1) {
#pragma unroll
                for (int i = 0; i < 4; i++)
                    part[i] += __shfl_xor_sync(0xffffffff, part[i], off);
            }
            if (cg == 0) {
#pragma unroll
                for (int i = 0; i < 4; i++) {
                    int el = row0 + i;
                    if (e0 + el < N_EDGES) {
                        float cw = part[i];
                        int r = rows_s[el];
                        atomicAdd(&d_cagg[r * 3 + 0], diffs[el * 3 + 0] * cw);
                        atomicAdd(&d_cagg[r * 3 + 1], diffs[el * 3 + 1] * cw);
                        atomicAdd(&d_cagg[r * 3 + 2], diffs[el * 3 + 2] * cw);
                    }
                }
            }
        }
        __syncthreads();
    }
}

// ---------------- coord update (and clear cagg) ----------------
__global__ void coord_kernel() {
    int n = blockIdx.x * blockDim.x + threadIdx.x;
    if (n < N_NODES) {
        float inv = 1.0f / fmaxf(d_deg[n], 1.0f);
#pragma unroll
        for (int dd = 0; dd < 3; dd++) {
            d_coord[n * 3 + dd] += d_cagg[n * 3 + dd] * inv;
            d_cagg[n * 3 + dd] = 0.0f;
        }
    }
}

// ---------------- global mean pool (batch is sorted) ----------------
__global__ void pool_kernel(const int* __restrict__ batch) {
    int n0 = blockIdx.x * 512;
    int ch = threadIdx.x;  // 128 threads
    if (n0 >= N_NODES) return;
    int nend = min(n0 + 512, N_NODES);
    int cur = batch[n0];
    float acc = 0.0f, cnt = 0.0f;
    for (int n = n0; n < nend; n++) {
        int g = batch[n];
        if (g != cur) {
            atomicAdd(&d_gsum[cur * HID + ch], acc);
            if (ch == 0) atomicAdd(&d_gcnt[cur], cnt);
            acc = 0.0f; cnt = 0.0f; cur = g;
        }
        acc += d_A[n * HID + ch];
        cnt += 1.0f;
    }
    atomicAdd(&d_gsum[cur * HID + ch], acc);
    if (ch == 0) atomicAdd(&d_gcnt[cur], cnt);
}

// ---------------- final fc ----------------
__global__ void fc_kernel(const float* __restrict__ fcw, const float* __restrict__ fcb,
                          float* __restrict__ out) {
    int g = blockIdx.x;
    int ch = threadIdx.x;  // 256
    float inv = 1.0f / fmaxf(d_gcnt[g], 1.0f);
    float acc = fcb[ch];
    for (int k = 0; k < HID; k++)
        acc += d_gsum[g * HID + k] * inv * fcw[k * OUT_DIM + ch];
    out[g * OUT_DIM + ch] = acc;
}

// ---------------- launch ----------------
#define GEMM_SMEM ((16384 + 64 * STRIDE + 128) * 4)
#define EDGE_SMEM ((16384 * 2 + 2 * 64 * STRIDE + 5 * 128 + 192) * 4 + 64 * 4)
#define GRID_G 296
#define GRID_E 148

extern "C" void kernel_launch(void* const* d_in, const int* in_sizes, int n_in,
                              void* d_out, int out_size) {
    const float* x = (const float*)d_in[0];
    const int* eidx = (const int*)d_in[1];
    const float* coord = (const float*)d_in[2];
    const float* ea = (const float*)d_in[3];
    const int* batch = (const int*)d_in[4];
    const float* emb_in_w = (const float*)d_in[5];
    const float* emb_in_b = (const float*)d_in[6];
    const float* edge_w1 = (const float*)d_in[7];
    const float* edge_b1 = (const float*)d_in[8];
    const float* edge_w2 = (const float*)d_in[9];
    const float* edge_b2 = (const float*)d_in[10];
    const float* node_w1 = (const float*)d_in[11];
    const float* node_b1 = (const float*)d_in[12];
    const float* node_w2 = (const float*)d_in[13];
    const float* node_b2 = (const float*)d_in[14];
    const float* coord_w1 = (const float*)d_in[15];
    const float* coord_b1 = (const float*)d_in[16];
    const float* coord_w2 = (const float*)d_in[17];
    const float* emb_out_w = (const float*)d_in[18];
    const float* emb_out_b = (const float*)d_in[19];
    const float* fc_w = (const float*)d_in[20];
    const float* fc_b = (const float*)d_in[21];
    float* out = (float*)d_out;

    const int* row = eidx;
    const int* col = eidx + N_EDGES;

    float *ph, *pA, *pB, *pT, *pmagg;
    cudaGetSymbolAddress((void**)&ph, d_h);
    cudaGetSymbolAddress((void**)&pA, d_A);
    cudaGetSymbolAddress((void**)&pB, d_B);
    cudaGetSymbolAddress((void**)&pT, d_T);
    cudaGetSymbolAddress((void**)&pmagg, d_magg);

    cudaFuncSetAttribute(edge_kernel, cudaFuncAttributeMaxDynamicSharedMemorySize, EDGE_SMEM);
    cudaFuncSetAttribute(gemm128_kernel, cudaFuncAttributeMaxDynamicSharedMemorySize, GEMM_SMEM);

    init_kernel<<<(N_NODES * HID + 255) / 256, 256>>>(coord);
    deg_kernel<<<(N_EDGES + 255) / 256, 256>>>(row);
    emb_in_kernel<<<(N_NODES * HID + 255) / 256, 256>>>(x, emb_in_w, emb_in_b);

    for (int l = 0; l < N_LAYERS; l++) {
        const float* W1 = edge_w1 + l * 258 * HID;
        // pre-projections: A = h@W1a + b1 ; B = h@W1b
        gemm128_kernel<<<GRID_G, 256, GEMM_SMEM>>>(ph, W1, edge_b1 + l * HID, pA, GM_BIAS);
        gemm128_kernel<<<GRID_G, 256, GEMM_SMEM>>>(ph, W1 + 128 * HID, nullptr, pB, 0);
        // fused edge MLP + aggregation
        edge_kernel<<<GRID_E, 256, EDGE_SMEM>>>(row, col, ea,
            edge_w2 + l * HID * HID, edge_b2 + l * HID,
            coord_w1 + l * HID * HID, coord_b1 + l * HID, coord_w2 + l * HID,
            W1 + 256 * HID, W1 + 257 * HID);
        // coord update
        coord_kernel<<<(N_NODES + 255) / 256, 256>>>();
        // node update: T = silu(h@nW1a + magg@nW1b + nb1); h += T@nW2 + nb2
        gemm128_kernel<<<GRID_G, 256, GEMM_SMEM>>>(ph, node_w1 + l * 256 * HID,
                                                   node_b1 + l * HID, pT, GM_BIAS);
        gemm128_kernel<<<GRID_G, 256, GEMM_SMEM>>>(pmagg, node_w1 + l * 256 * HID + 128 * HID,
                                                   nullptr, pT, GM_ACC | GM_SILU | GM_CLEARX);
        gemm128_kernel<<<GRID_G, 256, GEMM_SMEM>>>(pT, node_w2 + l * HID * HID,
                                                   node_b2 + l * HID, ph, GM_BIAS | GM_ACC);
    }

    // output embedding -> d_A
    gemm128_kernel<<<GRID_G, 256, GEMM_SMEM>>>(ph, emb_out_w, emb_out_b, pA, GM_BIAS);
    pool_kernel<<<(N_NODES + 511) / 512, 128>>>(batch);
    fc_kernel<<<N_GRAPHS, 256>>>(fc_w, fc_b, out);
}

// round 5
// speedup vs baseline: 1.0201x; 1.0201x over previous
#include <cuda_runtime.h>
#include <math.h>

#define N_NODES 50000
#define N_EDGES 600000
#define N_GRAPHS 64
#define HID 128
#define IN_DIM 16
#define OUT_DIM 256
#define N_LAYERS 3
#define STRIDE 132     // padded row stride (floats) for smem tiles
#define NTILES_E 9375  // 600000 / 64 exactly

typedef unsigned long long ull;

// ---------------- device scratch (static, no allocation) ----------------
__device__ float d_h[N_NODES * HID];
__device__ float d_A[N_NODES * HID];
__device__ float d_B[N_NODES * HID];
__device__ float d_T[N_NODES * HID];
__device__ float d_magg[N_NODES * HID];
__device__ float d_cagg[N_NODES * 3];
__device__ float d_coord[N_NODES * 3];
__device__ float d_deg[N_NODES];
__device__ float d_gsum[N_GRAPHS * HID];
__device__ float d_gcnt[N_GRAPHS];

__device__ __forceinline__ float silu_f(float x) {
    return x / (1.0f + __expf(-x));
}

__device__ __forceinline__ void fma2(ull& d, ull a, ull b) {
#if defined(CUDART_VERSION) && (CUDART_VERSION >= 12080)
    asm("fma.rn.f32x2 %0, %1, %2, %0;" : "+l"(d) : "l"(a), "l"(b));
#else
    float2 df, af, bf;
    df.x = __uint_as_float((unsigned)(d & 0xffffffffull));
    df.y = __uint_as_float((unsigned)(d >> 32));
    af.x = __uint_as_float((unsigned)(a & 0xffffffffull));
    af.y = __uint_as_float((unsigned)(a >> 32));
    bf.x = __uint_as_float((unsigned)(b & 0xffffffffull));
    bf.y = __uint_as_float((unsigned)(b >> 32));
    df.x = fmaf(af.x, bf.x, df.x);
    df.y = fmaf(af.y, bf.y, df.y);
    d = ((ull)__float_as_uint(df.y) << 32) | (ull)__float_as_uint(df.x);
#endif
}
__device__ __forceinline__ float sum2(ull v) {
    float2 f;
    f.x = __uint_as_float((unsigned)(v & 0xffffffffull));
    f.y = __uint_as_float((unsigned)(v >> 32));
    return f.x + f.y;
}

#define BAR_SYNC(id, cnt)   asm volatile("bar.sync %0, %1;"   :: "r"(id), "r"(cnt) : "memory")
#define BAR_ARRIVE(id, cnt) asm volatile("bar.arrive %0, %1;" :: "r"(id), "r"(cnt) : "memory")

// ---------------- init ----------------
__global__ void init_kernel(const float* __restrict__ coord_in) {
    int idx = blockIdx.x * blockDim.x + threadIdx.x;
    if (idx < N_NODES * HID) d_magg[idx] = 0.0f;
    if (idx < N_NODES * 3) { d_cagg[idx] = 0.0f; d_coord[idx] = coord_in[idx]; }
    if (idx < N_NODES) d_deg[idx] = 0.0f;
    if (idx < N_GRAPHS * HID) d_gsum[idx] = 0.0f;
    if (idx < N_GRAPHS) d_gcnt[idx] = 0.0f;
}

__global__ void deg_kernel(const int* __restrict__ row) {
    int e = blockIdx.x * blockDim.x + threadIdx.x;
    if (e < N_EDGES) atomicAdd(&d_deg[row[e]], 1.0f);
}

// ---------------- embedding in ----------------
__global__ void emb_in_kernel(const float* __restrict__ x,
                              const float* __restrict__ w,
                              const float* __restrict__ b) {
    int idx = blockIdx.x * blockDim.x + threadIdx.x;
    if (idx >= N_NODES * HID) return;
    int n = idx >> 7, ch = idx & 127;
    float acc = b[ch];
#pragma unroll
    for (int k = 0; k < IN_DIM; k++) acc += x[n * IN_DIM + k] * w[k * HID + ch];
    d_h[idx] = acc;
}

// ---------------- weight repack: [128][128] -> [64 k2][128 c][2 parity] ----------------
__device__ __forceinline__ void repack_w(const float* __restrict__ W, float* __restrict__ Wp,
                                         int tid, int nthreads) {
    for (int idx = tid; idx < 4096; idx += nthreads) {
        int k = idx >> 5;
        int c0 = (idx & 31) * 4;
        float4 v = reinterpret_cast<const float4*>(W)[idx];
        int k2 = k >> 1, p = k & 1;
        float* dst = &Wp[k2 * 256 + p];
        dst[(c0 + 0) * 2] = v.x;
        dst[(c0 + 1) * 2] = v.y;
        dst[(c0 + 2) * 2] = v.z;
        dst[(c0 + 3) * 2] = v.w;
    }
}

// ---------------- packed micro GEMM: 4 rows x 8 cols per thread (256 threads) ----------------
__device__ __forceinline__ void mgemm2(const float* __restrict__ Xs,
                                       const float* __restrict__ Wp,
                                       int row0, int cg, ull acc[4][4][2]) {
#pragma unroll
    for (int i = 0; i < 4; i++)
#pragma unroll
        for (int m = 0; m < 4; m++) { acc[i][m][0] = 0ull; acc[i][m][1] = 0ull; }
    const float* xb = Xs + row0 * STRIDE;
#pragma unroll 2
    for (int k2 = 0; k2 < 64; k2++) {
        ull x0 = *reinterpret_cast<const ull*>(xb + 0 * STRIDE + 2 * k2);
        ull x1 = *reinterpret_cast<const ull*>(xb + 1 * STRIDE + 2 * k2);
        ull x2 = *reinterpret_cast<const ull*>(xb + 2 * STRIDE + 2 * k2);
        ull x3 = *reinterpret_cast<const ull*>(xb + 3 * STRIDE + 2 * k2);
        const float* wrow = Wp + k2 * 256 + 4 * cg;
#pragma unroll
        for (int m = 0; m < 4; m++) {
            ulonglong2 wv = *reinterpret_cast<const ulonglong2*>(wrow + 64 * m);
            fma2(acc[0][m][0], x0, wv.x); fma2(acc[0][m][1], x0, wv.y);
            fma2(acc[1][m][0], x1, wv.x); fma2(acc[1][m][1], x1, wv.y);
            fma2(acc[2][m][0], x2, wv.x); fma2(acc[2][m][1], x2, wv.y);
            fma2(acc[3][m][0], x3, wv.x); fma2(acc[3][m][1], x3, wv.y);
        }
    }
}

// ---------------- generic node GEMM ----------------
#define GM_BIAS 1
#define GM_ACC 2
#define GM_SILU 4
#define GM_CLEARX 8
__global__ void __launch_bounds__(256, 2)
gemm128_kernel(float* __restrict__ X, const float* __restrict__ W,
               const float* __restrict__ bias, float* __restrict__ Y, int mode) {
    extern __shared__ float sm[];
    float* Wp = sm;
    float* Xs = sm + 16384;
    float* bs = Xs + 64 * STRIDE;
    int tid = threadIdx.x;
    repack_w(W, Wp, tid, 256);
    if (tid < 128) bs[tid] = (mode & GM_BIAS) ? bias[tid] : 0.0f;
    __syncthreads();

    int warp = tid >> 5, tx = tid & 31;
    int rh = tx >> 4, cg = tx & 15;
    int row0 = warp * 8 + rh * 4;

    int ntiles = (N_NODES + 63) / 64;
    for (int tile = blockIdx.x; tile < ntiles; tile += gridDim.x) {
        int r0 = tile * 64;
#pragma unroll
        for (int i = 0; i < 32; i++) {
            int idx = i * 256 + tid;
            int r = idx >> 7, k = idx & 127;
            int gr = r0 + r;
            float v = 0.0f;
            if (gr < N_NODES) {
                v = X[gr * HID + k];
                if (mode & GM_CLEARX) X[gr * HID + k] = 0.0f;
            }
            Xs[r * STRIDE + k] = v;
        }
        __syncthreads();
        ull acc[4][4][2];
        mgemm2(Xs, Wp, row0, cg, acc);
#pragma unroll
        for (int i = 0; i < 4; i++) {
            int gr = r0 + row0 + i;
            if (gr < N_NODES) {
#pragma unroll
                for (int m = 0; m < 4; m++) {
                    int c = 2 * cg + 32 * m;
                    float2 res;
                    res.x = sum2(acc[i][m][0]) + bs[c];
                    res.y = sum2(acc[i][m][1]) + bs[c + 1];
                    float* yp = &Y[gr * HID + c];
                    if (mode & GM_ACC) {
                        float2 o = *reinterpret_cast<float2*>(yp);
                        res.x += o.x; res.y += o.y;
                    }
                    if (mode & GM_SILU) { res.x = silu_f(res.x); res.y = silu_f(res.y); }
                    *reinterpret_cast<float2*>(yp) = res;
                }
            }
        }
        __syncthreads();
    }
}

// ---------------- warp-specialized edge kernel ----------------
// 384 threads: warps 0-7 consumers (GEMM B, GEMM C, cagg scatter),
//              warps 8-11 producers (gather+silu -> tS, magg scatter).
// Named barriers: 1 = tS full (P arrive, C sync), 2 = tS free (C arrive, P sync),
//                 3 = mS full (C arrive, P sync), 5 = consumer-internal.
__global__ void __launch_bounds__(384, 1)
edge_kernel(const int* __restrict__ row, const int* __restrict__ col,
            const float* __restrict__ ea,
            const float* __restrict__ W2, const float* __restrict__ b2,
            const float* __restrict__ Wc1, const float* __restrict__ bc1,
            const float* __restrict__ wc2,
            const float* __restrict__ wr, const float* __restrict__ we) {
    extern __shared__ float sm[];
    float* W2p = sm;                    // 16384
    float* Wc1p = W2p + 16384;          // 16384
    float* tS = Wc1p + 16384;           // 64*STRIDE
    float* mS = tS + 64 * STRIDE;       // 64*STRIDE
    float* b2s = mS + 64 * STRIDE;      // 128
    float* bc1s = b2s + 128;
    float* wc2s = bc1s + 128;
    float* wrs = wc2s + 128;
    float* wes = wrs + 128;
    float* diffs = wes + 128;           // 2 * 64*3
    int* rows_s = (int*)(diffs + 384);  // 2 * 64

    int tid = threadIdx.x;
    repack_w(W2, W2p, tid, 384);
    repack_w(Wc1, Wc1p, tid, 384);
    if (tid < 128) {
        b2s[tid] = b2[tid]; bc1s[tid] = bc1[tid]; wc2s[tid] = wc2[tid];
        wrs[tid] = wr[tid]; wes[tid] = we[tid];
    }
    __syncthreads();

    int nloc = (NTILES_E - blockIdx.x + gridDim.x - 1) / gridDim.x;

    if (tid >= 256) {
        // ================= PRODUCERS (128 threads) =================
        int p = tid - 256;
        int e_loc = p >> 1;       // 0..63
        int q = p & 1;            // channel half

        // gather tile i into tS / rows_s[buf] / diffs[buf]
        auto gather = [&](int i) {
            int buf = i & 1;
            int e = (blockIdx.x + i * gridDim.x) * 64 + e_loc;
            int r = row[e], c = col[e];
            float dx = d_coord[r * 3 + 0] - d_coord[c * 3 + 0];
            float dy = d_coord[r * 3 + 1] - d_coord[c * 3 + 1];
            float dz = d_coord[r * 3 + 2] - d_coord[c * 3 + 2];
            float radial = dx * dx + dy * dy + dz * dz;
            float eav = ea[e];
            if (q == 0) {
                rows_s[buf * 64 + e_loc] = r;
                diffs[buf * 192 + e_loc * 3 + 0] = dx;
                diffs[buf * 192 + e_loc * 3 + 1] = dy;
                diffs[buf * 192 + e_loc * 3 + 2] = dz;
            }
#pragma unroll
            for (int jj = 0; jj < 16; jj++) {
                int ch = q * 64 + jj * 4;
                float4 av = *reinterpret_cast<const float4*>(&d_A[r * HID + ch]);
                float4 bv = *reinterpret_cast<const float4*>(&d_B[c * HID + ch]);
                float4 w1 = *reinterpret_cast<const float4*>(&wrs[ch]);
                float4 w2v = *reinterpret_cast<const float4*>(&wes[ch]);
                float4 tv;
                tv.x = silu_f(av.x + bv.x + radial * w1.x + eav * w2v.x);
                tv.y = silu_f(av.y + bv.y + radial * w1.y + eav * w2v.y);
                tv.z = silu_f(av.z + bv.z + radial * w1.z + eav * w2v.z);
                tv.w = silu_f(av.w + bv.w + radial * w1.w + eav * w2v.w);
                *reinterpret_cast<float4*>(&tS[e_loc * STRIDE + ch]) = tv;
            }
        };

        gather(0);
        __threadfence_block();
        BAR_ARRIVE(1, 384);
        for (int i = 0; i < nloc; i++) {
            int buf = i & 1;
            BAR_SYNC(3, 384);                 // mS(i) full
            // scatter magg from mS
            const int* rs = &rows_s[buf * 64];
#pragma unroll 8
            for (int idx = p; idx < 8192; idx += 128) {
                int el = idx >> 7, ch = idx & 127;
                atomicAdd(&d_magg[rs[el] * HID + ch], mS[el * STRIDE + ch]);
            }
            if (i + 1 < nloc) {
                BAR_SYNC(2, 384);             // tS free
                gather(i + 1);
                __threadfence_block();
                BAR_ARRIVE(1, 384);
            }
        }
    } else {
        // ================= CONSUMERS (256 threads) =================
        int warp = tid >> 5, tx = tid & 31;
        int rh = tx >> 4, cg = tx & 15;
        int row0 = warp * 8 + rh * 4;

        for (int i = 0; i < nloc; i++) {
            int buf = i & 1;
            BAR_SYNC(1, 384);                 // tS(i) full (also consumer-consumer sync)
            // ---- B: m = silu(tS @ W2 + b2) ----
            ull acc[4][4][2];
            mgemm2(tS, W2p, row0, cg, acc);
            if (i + 1 < nloc) BAR_ARRIVE(2, 384);  // done reading tS
#pragma unroll
            for (int ii = 0; ii < 4; ii++) {
#pragma unroll
                for (int m = 0; m < 4; m++) {
                    int c = 2 * cg + 32 * m;
                    float2 mv;
                    mv.x = silu_f(sum2(acc[ii][m][0]) + b2s[c]);
                    mv.y = silu_f(sum2(acc[ii][m][1]) + b2s[c + 1]);
                    *reinterpret_cast<float2*>(&mS[(row0 + ii) * STRIDE + c]) = mv;
                }
            }
            BAR_SYNC(5, 256);                 // mS visible to all consumers
            BAR_ARRIVE(3, 384);               // producers: scatter magg now
            // ---- C: cw = silu(mS @ Wc1 + bc1) . wc2 ; scatter cagg ----
            ull acc2[4][4][2];
            mgemm2(mS, Wc1p, row0, cg, acc2);
            float part[4];
#pragma unroll
            for (int ii = 0; ii < 4; ii++) {
                part[ii] = 0.0f;
#pragma unroll
                for (int m = 0; m < 4; m++) {
                    int c = 2 * cg + 32 * m;
                    part[ii] += silu_f(sum2(acc2[ii][m][0]) + bc1s[c]) * wc2s[c];
                    part[ii] += silu_f(sum2(acc2[ii][m][1]) + bc1s[c + 1]) * wc2s[c + 1];
                }
            }
#pragma unroll
            for (int off = 8; off > 0; off >>= 1) {
#pragma unroll
                for (int ii = 0; ii < 4; ii++)
                    part[ii] += __shfl_xor_sync(0xffffffff, part[ii], off);
            }
            if (cg == 0) {
#pragma unroll
                for (int ii = 0; ii < 4; ii++) {
                    int el = row0 + ii;
                    float cw = part[ii];
                    int r = rows_s[buf * 64 + el];
                    const float* df = &diffs[buf * 192 + el * 3];
                    atomicAdd(&d_cagg[r * 3 + 0], df[0] * cw);
                    atomicAdd(&d_cagg[r * 3 + 1], df[1] * cw);
                    atomicAdd(&d_cagg[r * 3 + 2], df[2] * cw);
                }
            }
        }
    }
}

// ---------------- coord update ----------------
__global__ void coord_kernel() {
    int n = blockIdx.x * blockDim.x + threadIdx.x;
    if (n < N_NODES) {
        float inv = 1.0f / fmaxf(d_deg[n], 1.0f);
#pragma unroll
        for (int dd = 0; dd < 3; dd++) {
            d_coord[n * 3 + dd] += d_cagg[n * 3 + dd] * inv;
            d_cagg[n * 3 + dd] = 0.0f;
        }
    }
}

// ---------------- global mean pool ----------------
__global__ void pool_kernel(const int* __restrict__ batch) {
    int n0 = blockIdx.x * 512;
    int ch = threadIdx.x;
    if (n0 >= N_NODES) return;
    int nend = min(n0 + 512, N_NODES);
    int cur = batch[n0];
    float acc = 0.0f, cnt = 0.0f;
    for (int n = n0; n < nend; n++) {
        int g = batch[n];
        if (g != cur) {
            atomicAdd(&d_gsum[cur * HID + ch], acc);
            if (ch == 0) atomicAdd(&d_gcnt[cur], cnt);
            acc = 0.0f; cnt = 0.0f; cur = g;
        }
        acc += d_A[n * HID + ch];
        cnt += 1.0f;
    }
    atomicAdd(&d_gsum[cur * HID + ch], acc);
    if (ch == 0) atomicAdd(&d_gcnt[cur], cnt);
}

// ---------------- final fc ----------------
__global__ void fc_kernel(const float* __restrict__ fcw, const float* __restrict__ fcb,
                          float* __restrict__ out) {
    int g = blockIdx.x;
    int ch = threadIdx.x;
    float inv = 1.0f / fmaxf(d_gcnt[g], 1.0f);
    float acc = fcb[ch];
    for (int k = 0; k < HID; k++)
        acc += d_gsum[g * HID + k] * inv * fcw[k * OUT_DIM + ch];
    out[g * OUT_DIM + ch] = acc;
}

// ---------------- launch ----------------
#define GEMM_SMEM ((16384 + 64 * STRIDE + 128) * 4)
#define EDGE_SMEM ((16384 * 2 + 2 * 64 * STRIDE + 5 * 128 + 384) * 4 + 2 * 64 * 4)
#define GRID_G 296
#define GRID_E 148

extern "C" void kernel_launch(void* const* d_in, const int* in_sizes, int n_in,
                              void* d_out, int out_size) {
    const float* x = (const float*)d_in[0];
    const int* eidx = (const int*)d_in[1];
    const float* coord = (const float*)d_in[2];
    const float* ea = (const float*)d_in[3];
    const int* batch = (const int*)d_in[4];
    const float* emb_in_w = (const float*)d_in[5];
    const float* emb_in_b = (const float*)d_in[6];
    const float* edge_w1 = (const float*)d_in[7];
    const float* edge_b1 = (const float*)d_in[8];
    const float* edge_w2 = (const float*)d_in[9];
    const float* edge_b2 = (const float*)d_in[10];
    const float* node_w1 = (const float*)d_in[11];
    const float* node_b1 = (const float*)d_in[12];
    const float* node_w2 = (const float*)d_in[13];
    const float* node_b2 = (const float*)d_in[14];
    const float* coord_w1 = (const float*)d_in[15];
    const float* coord_b1 = (const float*)d_in[16];
    const float* coord_w2 = (const float*)d_in[17];
    const float* emb_out_w = (const float*)d_in[18];
    const float* emb_out_b = (const float*)d_in[19];
    const float* fc_w = (const float*)d_in[20];
    const float* fc_b = (const float*)d_in[21];
    float* out = (float*)d_out;

    const int* row = eidx;
    const int* col = eidx + N_EDGES;

    float *ph, *pA, *pB, *pT, *pmagg;
    cudaGetSymbolAddress((void**)&ph, d_h);
    cudaGetSymbolAddress((void**)&pA, d_A);
    cudaGetSymbolAddress((void**)&pB, d_B);
    cudaGetSymbolAddress((void**)&pT, d_T);
    cudaGetSymbolAddress((void**)&pmagg, d_magg);

    cudaFuncSetAttribute(edge_kernel, cudaFuncAttributeMaxDynamicSharedMemorySize, EDGE_SMEM);
    cudaFuncSetAttribute(gemm128_kernel, cudaFuncAttributeMaxDynamicSharedMemorySize, GEMM_SMEM);

    init_kernel<<<(N_NODES * HID + 255) / 256, 256>>>(coord);
    deg_kernel<<<(N_EDGES + 255) / 256, 256>>>(row);
    emb_in_kernel<<<(N_NODES * HID + 255) / 256, 256>>>(x, emb_in_w, emb_in_b);

    for (int l = 0; l < N_LAYERS; l++) {
        const float* W1 = edge_w1 + l * 258 * HID;
        gemm128_kernel<<<GRID_G, 256, GEMM_SMEM>>>(ph, W1, edge_b1 + l * HID, pA, GM_BIAS);
        gemm128_kernel<<<GRID_G, 256, GEMM_SMEM>>>(ph, W1 + 128 * HID, nullptr, pB, 0);
        edge_kernel<<<GRID_E, 384, EDGE_SMEM>>>(row, col, ea,
            edge_w2 + l * HID * HID, edge_b2 + l * HID,
            coord_w1 + l * HID * HID, coord_b1 + l * HID, coord_w2 + l * HID,
            W1 + 256 * HID, W1 + 257 * HID);
        coord_kernel<<<(N_NODES + 255) / 256, 256>>>();
        gemm128_kernel<<<GRID_G, 256, GEMM_SMEM>>>(ph, node_w1 + l * 256 * HID,
                                                   node_b1 + l * HID, pT, GM_BIAS);
        gemm128_kernel<<<GRID_G, 256, GEMM_SMEM>>>(pmagg, node_w1 + l * 256 * HID + 128 * HID,
                                                   nullptr, pT, GM_ACC | GM_SILU | GM_CLEARX);
        gemm128_kernel<<<GRID_G, 256, GEMM_SMEM>>>(pT, node_w2 + l * HID * HID,
                                                   node_b2 + l * HID, ph, GM_BIAS | GM_ACC);
    }

    gemm128_kernel<<<GRID_G, 256, GEMM_SMEM>>>(ph, emb_out_w, emb_out_b, pA, GM_BIAS);
    pool_kernel<<<(N_NODES + 511) / 512, 128>>>(batch);
    fc_kernel<<<N_GRAPHS, 256>>>(fc_w, fc_b, out);
}

// round 7
// speedup vs baseline: 1.8154x; 1.7797x over previous
#include <cuda_runtime.h>
#include <math.h>
#include <stdint.h>

#define N_NODES 50000
#define N_EDGES 600000
#define N_GRAPHS 64
#define HID 128
#define IN_DIM 16
#define OUT_DIM 256
#define N_LAYERS 3
#define NT_E 9375            // 600000 / 64
#define NT_N 782             // ceil(50000/64)

// ---------------- device scratch ----------------
__device__ float d_h[N_NODES * HID];
__device__ float d_A[N_NODES * HID];
__device__ float d_B[N_NODES * HID];
__device__ float d_T[N_NODES * HID];
__device__ float d_magg[N_NODES * HID];
__device__ float d_cagg[N_NODES * 3];
__device__ float d_coord[N_NODES * 3];
__device__ float d_deg[N_NODES];
__device__ float d_gsum[N_GRAPHS * HID];
__device__ float d_gcnt[N_GRAPHS];
__device__ float d_WtA[HID * HID];   // transposed-weight staging
__device__ float d_WtB[HID * HID];

__device__ __forceinline__ float silu_f(float x) {
    return x / (1.0f + __expf(-x));
}
__device__ __forceinline__ uint32_t smem_u32(const void* p) {
    uint32_t a;
    asm("{ .reg .u64 t; cvta.to.shared.u64 t, %1; cvt.u32.u64 %0, t; }" : "=r"(a) : "l"(p));
    return a;
}
__device__ __forceinline__ uint32_t to_tf32(float f) {
    uint32_t o;
    asm("cvt.rna.tf32.f32 %0, %1;" : "=r"(o) : "f"(f));
    return o;
}
__device__ __forceinline__ void ldsm_x4(uint32_t a[4], uint32_t addr) {
    asm volatile("ldmatrix.sync.aligned.m8n8.x4.shared.b16 {%0,%1,%2,%3}, [%4];"
        : "=r"(a[0]), "=r"(a[1]), "=r"(a[2]), "=r"(a[3]) : "r"(addr));
}
__device__ __forceinline__ void ldsm_x2(uint32_t b[2], uint32_t addr) {
    asm volatile("ldmatrix.sync.aligned.m8n8.x2.shared.b16 {%0,%1}, [%2];"
        : "=r"(b[0]), "=r"(b[1]) : "r"(addr));
}
__device__ __forceinline__ void mma_tf32(float d[4], const uint32_t a[4], const uint32_t b[2]) {
    asm volatile("mma.sync.aligned.m16n8k8.row.col.f32.tf32.tf32.f32 "
        "{%0,%1,%2,%3}, {%4,%5,%6,%7}, {%8,%9}, {%0,%1,%2,%3};"
        : "+f"(d[0]), "+f"(d[1]), "+f"(d[2]), "+f"(d[3])
        : "r"(a[0]), "r"(a[1]), "r"(a[2]), "r"(a[3]), "r"(b[0]), "r"(b[1]));
}

// ---------------- small kernels ----------------
__global__ void init_kernel(const float* __restrict__ coord_in) {
    int idx = blockIdx.x * blockDim.x + threadIdx.x;
    if (idx < N_NODES * HID) d_magg[idx] = 0.0f;
    if (idx < N_NODES * 3) { d_cagg[idx] = 0.0f; d_coord[idx] = coord_in[idx]; }
    if (idx < N_NODES) d_deg[idx] = 0.0f;
    if (idx < N_GRAPHS * HID) d_gsum[idx] = 0.0f;
    if (idx < N_GRAPHS) d_gcnt[idx] = 0.0f;
}

__global__ void deg_kernel(const int* __restrict__ row) {
    int e = blockIdx.x * blockDim.x + threadIdx.x;
    if (e < N_EDGES) atomicAdd(&d_deg[row[e]], 1.0f);
}

__global__ void emb_in_kernel(const float* __restrict__ x,
                              const float* __restrict__ w,
                              const float* __restrict__ b) {
    int idx = blockIdx.x * blockDim.x + threadIdx.x;
    if (idx >= N_NODES * HID) return;
    int n = idx >> 7, ch = idx & 127;
    float acc = b[ch];
#pragma unroll
    for (int k = 0; k < IN_DIM; k++) acc += x[n * IN_DIM + k] * w[k * HID + ch];
    d_h[idx] = acc;
}

// 128x128 transpose: Wt[c][k] = W[k][c].  grid 16, block (32,8)
__global__ void wtrans_kernel(const float* __restrict__ W, float* __restrict__ Wt) {
    __shared__ float t[32][33];
    int bx = blockIdx.x & 3, by = blockIdx.x >> 2;
    int x = bx * 32 + threadIdx.x;
    int y0 = by * 32 + threadIdx.y;
#pragma unroll
    for (int dy = 0; dy < 32; dy += 8)
        t[threadIdx.y + dy][threadIdx.x] = W[(y0 + dy) * HID + x];
    __syncthreads();
    int xo = by * 32 + threadIdx.x;
    int yo = bx * 32 + threadIdx.y;
#pragma unroll
    for (int dy = 0; dy < 32; dy += 8)
        Wt[(yo + dy) * HID + xo] = t[threadIdx.x][threadIdx.y + dy];
}

// ---------------- mma node GEMM: Y = op(X@W (+bias) (+Y)) ----------------
// smem: Wts [128][132] @0, Xs [64][132] @16896, bs @25344
#define GEMM_SMEM ((16896 + 8448 + 128) * 4)
#define GM_BIAS 1
#define GM_ACC 2
#define GM_SILU 4
#define GM_CLEARX 8

__global__ void __launch_bounds__(256, 1)
gemm_mma(float* __restrict__ X, const float* __restrict__ WtG,
         const float* __restrict__ bias, float* __restrict__ Y, int mode) {
    extern __shared__ float sm[];
    float* Wts = sm;
    float* Xs = sm + 16896;
    float* bs = sm + 25344;
    int tid = threadIdx.x;

    for (int idx = tid; idx < 4096; idx += 256) {
        int c = idx >> 5, k4 = (idx & 31) * 4;
        float4 v = reinterpret_cast<const float4*>(WtG)[idx];
        uint4 t;
        t.x = to_tf32(v.x); t.y = to_tf32(v.y); t.z = to_tf32(v.z); t.w = to_tf32(v.w);
        *reinterpret_cast<uint4*>(&Wts[c * 132 + k4]) = t;
    }
    if (tid < 128) bs[tid] = (mode & GM_BIAS) ? bias[tid] : 0.0f;
    __syncthreads();

    uint32_t XsA = smem_u32(Xs), WtA = smem_u32(Wts);
    int L = tid & 31, w = tid >> 5;
    int mw = w & 1, nwg = w >> 1;
    int aRow = ((L >> 3) & 1) * 8 + (L & 7);
    uint32_t aBase0 = XsA + (uint32_t)(mw * 32 + aRow) * 528 + (uint32_t)(L >> 4) * 16;
    uint32_t aBase1 = aBase0 + 16 * 528;
    int Ln = L & 15;
    uint32_t bBase[4];
#pragma unroll
    for (int j = 0; j < 4; j++)
        bBase[j] = WtA + (uint32_t)((nwg * 4 + j) * 8 + (Ln & 7)) * 528 + (uint32_t)(Ln >> 3) * 16;

    for (int tile = blockIdx.x; tile < NT_N; tile += gridDim.x) {
        int r0 = tile * 64;
        for (int idx = tid; idx < 2048; idx += 256) {
            int r = idx >> 5, k4 = (idx & 31) * 4;
            int gr = r0 + r;
            float4 v = make_float4(0.f, 0.f, 0.f, 0.f);
            if (gr < N_NODES) {
                v = *reinterpret_cast<const float4*>(&X[gr * HID + k4]);
                if (mode & GM_CLEARX)
                    *reinterpret_cast<float4*>(&X[gr * HID + k4]) = make_float4(0.f, 0.f, 0.f, 0.f);
            }
            uint4 t;
            t.x = to_tf32(v.x); t.y = to_tf32(v.y); t.z = to_tf32(v.z); t.w = to_tf32(v.w);
            *reinterpret_cast<uint4*>(&Xs[r * 132 + k4]) = t;
        }
        __syncthreads();

        float acc[2][4][4];
#pragma unroll
        for (int i = 0; i < 2; i++)
#pragma unroll
            for (int j = 0; j < 4; j++)
#pragma unroll
                for (int e = 0; e < 4; e++) acc[i][j][e] = 0.0f;

#pragma unroll
        for (int kc = 0; kc < 16; kc++) {
            uint32_t a0[4], a1[4];
            ldsm_x4(a0, aBase0 + kc * 32);
            ldsm_x4(a1, aBase1 + kc * 32);
#pragma unroll
            for (int j = 0; j < 4; j++) {
                uint32_t b[2];
                ldsm_x2(b, bBase[j] + kc * 32);
                mma_tf32(acc[0][j], a0, b);
                mma_tf32(acc[1][j], a1, b);
            }
        }

#pragma unroll
        for (int i = 0; i < 2; i++) {
#pragma unroll
            for (int half = 0; half < 2; half++) {
                int gr = r0 + mw * 32 + i * 16 + half * 8 + (L >> 2);
                if (gr < N_NODES) {
#pragma unroll
                    for (int j = 0; j < 4; j++) {
                        int c = nwg * 32 + j * 8 + (L & 3) * 2;
                        float2 res;
                        res.x = acc[i][j][half * 2 + 0] + bs[c];
                        res.y = acc[i][j][half * 2 + 1] + bs[c + 1];
                        float* yp = &Y[gr * HID + c];
                        if (mode & GM_ACC) {
                            float2 o = *reinterpret_cast<float2*>(yp);
                            res.x += o.x; res.y += o.y;
                        }
                        if (mode & GM_SILU) { res.x = silu_f(res.x); res.y = silu_f(res.y); }
                        *reinterpret_cast<float2*>(yp) = res;
                    }
                }
            }
        }
        __syncthreads();
    }
}

// ---------------- mma edge kernel ----------------
// smem floats: W2s@0 [128][132], Wc1s@16896, tS@33792 [64][132], mS@42240,
// b2s@50688, bc1s@50816, wc2s@50944, wrs@51072, wes@51200,
// diffs@51328 (192), cw_part@51520 (256), rows_s@51776 (64 int)
#define EDGE_SMEM (51840 * 4)

__global__ void __launch_bounds__(256, 1)
edge_mma(const int* __restrict__ row, const int* __restrict__ col,
         const float* __restrict__ ea,
         const float* __restrict__ W2tG, const float* __restrict__ b2,
         const float* __restrict__ Wc1tG, const float* __restrict__ bc1,
         const float* __restrict__ wc2,
         const float* __restrict__ wr, const float* __restrict__ we) {
    extern __shared__ float sm[];
    float* W2s = sm;
    float* Wc1s = sm + 16896;
    float* tS = sm + 33792;
    float* mS = sm + 42240;
    float* b2s = sm + 50688;
    float* bc1s = sm + 50816;
    float* wc2s = sm + 50944;
    float* wrs = sm + 51072;
    float* wes = sm + 51200;
    float* diffs = sm + 51328;
    float* cw_part = sm + 51520;
    int* rows_s = (int*)(sm + 51776);

    int tid = threadIdx.x;
    for (int idx = tid; idx < 4096; idx += 256) {
        int c = idx >> 5, k4 = (idx & 31) * 4;
        float4 v = reinterpret_cast<const float4*>(W2tG)[idx];
        uint4 t;
        t.x = to_tf32(v.x); t.y = to_tf32(v.y); t.z = to_tf32(v.z); t.w = to_tf32(v.w);
        *reinterpret_cast<uint4*>(&W2s[c * 132 + k4]) = t;
        float4 u = reinterpret_cast<const float4*>(Wc1tG)[idx];
        uint4 s;
        s.x = to_tf32(u.x); s.y = to_tf32(u.y); s.z = to_tf32(u.z); s.w = to_tf32(u.w);
        *reinterpret_cast<uint4*>(&Wc1s[c * 132 + k4]) = s;
    }
    if (tid < 128) {
        b2s[tid] = b2[tid]; bc1s[tid] = bc1[tid]; wc2s[tid] = wc2[tid];
        wrs[tid] = wr[tid]; wes[tid] = we[tid];
    }
    __syncthreads();

    uint32_t tSA = smem_u32(tS), mSA = smem_u32(mS);
    uint32_t W2A = smem_u32(W2s), Wc1A = smem_u32(Wc1s);
    int L = tid & 31, w = tid >> 5;
    int mw = w & 1, nwg = w >> 1;
    int aRow = ((L >> 3) & 1) * 8 + (L & 7);
    uint32_t aOff = (uint32_t)(mw * 32 + aRow) * 528 + (uint32_t)(L >> 4) * 16;
    int Ln = L & 15;
    uint32_t bOff[4];
#pragma unroll
    for (int j = 0; j < 4; j++)
        bOff[j] = (uint32_t)((nwg * 4 + j) * 8 + (Ln & 7)) * 528 + (uint32_t)(Ln >> 3) * 16;

    int e_loc = tid & 63, q = tid >> 6;

    for (int tile = blockIdx.x; tile < NT_E; tile += gridDim.x) {
        int e0 = tile * 64;
        // ---- gather: tS = tf32(silu(A[r] + B[c] + radial*wr + ea*we)) ----
        {
            int e = e0 + e_loc;
            int r = row[e], c = col[e];
            float dx = d_coord[r * 3 + 0] - d_coord[c * 3 + 0];
            float dy = d_coord[r * 3 + 1] - d_coord[c * 3 + 1];
            float dz = d_coord[r * 3 + 2] - d_coord[c * 3 + 2];
            float radial = dx * dx + dy * dy + dz * dz;
            float eav = ea[e];
            if (q == 0) {
                rows_s[e_loc] = r;
                diffs[e_loc * 3 + 0] = dx; diffs[e_loc * 3 + 1] = dy; diffs[e_loc * 3 + 2] = dz;
            }
#pragma unroll
            for (int jj = 0; jj < 8; jj++) {
                int ch = q * 32 + jj * 4;
                float4 av = *reinterpret_cast<const float4*>(&d_A[r * HID + ch]);
                float4 bv = *reinterpret_cast<const float4*>(&d_B[c * HID + ch]);
                float4 w1 = *reinterpret_cast<const float4*>(&wrs[ch]);
                float4 w2v = *reinterpret_cast<const float4*>(&wes[ch]);
                uint4 t;
                t.x = to_tf32(silu_f(av.x + bv.x + radial * w1.x + eav * w2v.x));
                t.y = to_tf32(silu_f(av.y + bv.y + radial * w1.y + eav * w2v.y));
                t.z = to_tf32(silu_f(av.z + bv.z + radial * w1.z + eav * w2v.z));
                t.w = to_tf32(silu_f(av.w + bv.w + radial * w1.w + eav * w2v.w));
                *reinterpret_cast<uint4*>(&tS[e_loc * 132 + ch]) = t;
            }
        }
        __syncthreads();

        // ---- MMA1: D1 = tS @ W2^T ----
        float acc[2][4][4];
#pragma unroll
        for (int i = 0; i < 2; i++)
#pragma unroll
            for (int j = 0; j < 4; j++)
#pragma unroll
                for (int e = 0; e < 4; e++) acc[i][j][e] = 0.0f;
#pragma unroll
        for (int kc = 0; kc < 16; kc++) {
            uint32_t a0[4], a1[4];
            ldsm_x4(a0, tSA + aOff + kc * 32);
            ldsm_x4(a1, tSA + aOff + 16 * 528 + kc * 32);
#pragma unroll
            for (int j = 0; j < 4; j++) {
                uint32_t b[2];
                ldsm_x2(b, W2A + bOff[j] + kc * 32);
                mma_tf32(acc[0][j], a0, b);
                mma_tf32(acc[1][j], a1, b);
            }
        }

        // ---- epilogue1: m = silu(D1 + b2); magg atomics; mS <- tf32(m) ----
#pragma unroll
        for (int i = 0; i < 2; i++) {
#pragma unroll
            for (int half = 0; half < 2; half++) {
                int rowl = mw * 32 + i * 16 + half * 8 + (L >> 2);
                int rn = rows_s[rowl];
#pragma unroll
                for (int j = 0; j < 4; j++) {
                    int c = nwg * 32 + j * 8 + (L & 3) * 2;
                    float m0 = silu_f(acc[i][j][half * 2 + 0] + b2s[c]);
                    float m1 = silu_f(acc[i][j][half * 2 + 1] + b2s[c + 1]);
                    atomicAdd(&d_magg[rn * HID + c + 0], m0);
                    atomicAdd(&d_magg[rn * HID + c + 1], m1);
                    uint2 t;
                    t.x = to_tf32(m0); t.y = to_tf32(m1);
                    *reinterpret_cast<uint2*>(&mS[rowl * 132 + c]) = t;
                }
            }
        }
        __syncthreads();

        // ---- MMA2: D2 = mS @ Wc1^T ----
#pragma unroll
        for (int i = 0; i < 2; i++)
#pragma unroll
            for (int j = 0; j < 4; j++)
#pragma unroll
                for (int e = 0; e < 4; e++) acc[i][j][e] = 0.0f;
#pragma unroll
        for (int kc = 0; kc < 16; kc++) {
            uint32_t a0[4], a1[4];
            ldsm_x4(a0, mSA + aOff + kc * 32);
            ldsm_x4(a1, mSA + aOff + 16 * 528 + kc * 32);
#pragma unroll
            for (int j = 0; j < 4; j++) {
                uint32_t b[2];
                ldsm_x2(b, Wc1A + bOff[j] + kc * 32);
                mma_tf32(acc[0][j], a0, b);
                mma_tf32(acc[1][j], a1, b);
            }
        }

        // ---- epilogue2: cw = sum_c silu(D2 + bc1)*wc2 ----
#pragma unroll
        for (int i = 0; i < 2; i++) {
#pragma unroll
            for (int half = 0; half < 2; half++) {
                float p = 0.0f;
#pragma unroll
                for (int j = 0; j < 4; j++) {
                    int c = nwg * 32 + j * 8 + (L & 3) * 2;
                    p += silu_f(acc[i][j][half * 2 + 0] + bc1s[c]) * wc2s[c];
                    p += silu_f(acc[i][j][half * 2 + 1] + bc1s[c + 1]) * wc2s[c + 1];
                }
                p += __shfl_xor_sync(0xffffffff, p, 1);
                p += __shfl_xor_sync(0xffffffff, p, 2);
                if ((L & 3) == 0) {
                    int rowl = mw * 32 + i * 16 + half * 8 + (L >> 2);
                    cw_part[nwg * 64 + rowl] = p;
                }
            }
        }
        __syncthreads();
        if (tid < 64) {
            float cw = cw_part[tid] + cw_part[64 + tid] + cw_part[128 + tid] + cw_part[192 + tid];
            int rn = rows_s[tid];
            atomicAdd(&d_cagg[rn * 3 + 0], diffs[tid * 3 + 0] * cw);
            atomicAdd(&d_cagg[rn * 3 + 1], diffs[tid * 3 + 1] * cw);
            atomicAdd(&d_cagg[rn * 3 + 2], diffs[tid * 3 + 2] * cw);
        }
        __syncthreads();
    }
}

// ---------------- coord update ----------------
__global__ void coord_kernel() {
    int n = blockIdx.x * blockDim.x + threadIdx.x;
    if (n < N_NODES) {
        float inv = 1.0f / fmaxf(d_deg[n], 1.0f);
#pragma unroll
        for (int dd = 0; dd < 3; dd++) {
            d_coord[n * 3 + dd] += d_cagg[n * 3 + dd] * inv;
            d_cagg[n * 3 + dd] = 0.0f;
        }
    }
}

// ---------------- global mean pool ----------------
__global__ void pool_kernel(const int* __restrict__ batch) {
    int n0 = blockIdx.x * 512;
    int ch = threadIdx.x;
    if (n0 >= N_NODES) return;
    int nend = min(n0 + 512, N_NODES);
    int cur = batch[n0];
    float acc = 0.0f, cnt = 0.0f;
    for (int n = n0; n < nend; n++) {
        int g = batch[n];
        if (g != cur) {
            atomicAdd(&d_gsum[cur * HID + ch], acc);
            if (ch == 0) atomicAdd(&d_gcnt[cur], cnt);
            acc = 0.0f; cnt = 0.0f; cur = g;
        }
        acc += d_A[n * HID + ch];
        cnt += 1.0f;
    }
    atomicAdd(&d_gsum[cur * HID + ch], acc);
    if (ch == 0) atomicAdd(&d_gcnt[cur], cnt);
}

// ---------------- final fc ----------------
__global__ void fc_kernel(const float* __restrict__ fcw, const float* __restrict__ fcb,
                          float* __restrict__ out) {
    int g = blockIdx.x;
    int ch = threadIdx.x;
    float inv = 1.0f / fmaxf(d_gcnt[g], 1.0f);
    float acc = fcb[ch];
    for (int k = 0; k < HID; k++)
        acc += d_gsum[g * HID + k] * inv * fcw[k * OUT_DIM + ch];
    out[g * OUT_DIM + ch] = acc;
}

// ---------------- launch ----------------
#define GRID_G 148
#define GRID_E 148

extern "C" void kernel_launch(void* const* d_in, const int* in_sizes, int n_in,
                              void* d_out, int out_size) {
    const float* x = (const float*)d_in[0];
    const int* eidx = (const int*)d_in[1];
    const float* coord = (const float*)d_in[2];
    const float* ea = (const float*)d_in[3];
    const int* batch = (const int*)d_in[4];
    const float* emb_in_w = (const float*)d_in[5];
    const float* emb_in_b = (const float*)d_in[6];
    const float* edge_w1 = (const float*)d_in[7];
    const float* edge_b1 = (const float*)d_in[8];
    const float* edge_w2 = (const float*)d_in[9];
    const float* edge_b2 = (const float*)d_in[10];
    const float* node_w1 = (const float*)d_in[11];
    const float* node_b1 = (const float*)d_in[12];
    const float* node_w2 = (const float*)d_in[13];
    const float* node_b2 = (const float*)d_in[14];
    const float* coord_w1 = (const float*)d_in[15];
    const float* coord_b1 = (const float*)d_in[16];
    const float* coord_w2 = (const float*)d_in[17];
    const float* emb_out_w = (const float*)d_in[18];
    const float* emb_out_b = (const float*)d_in[19];
    const float* fc_w = (const float*)d_in[20];
    const float* fc_b = (const float*)d_in[21];
    float* out = (float*)d_out;

    const int* row = eidx;
    const int* col = eidx + N_EDGES;

    float *ph, *pA, *pB, *pT, *pmagg, *pWtA, *pWtB;
    cudaGetSymbolAddress((void**)&ph, d_h);
    cudaGetSymbolAddress((void**)&pA, d_A);
    cudaGetSymbolAddress((void**)&pB, d_B);
    cudaGetSymbolAddress((void**)&pT, d_T);
    cudaGetSymbolAddress((void**)&pmagg, d_magg);
    cudaGetSymbolAddress((void**)&pWtA, d_WtA);
    cudaGetSymbolAddress((void**)&pWtB, d_WtB);

    cudaFuncSetAttribute(edge_mma, cudaFuncAttributeMaxDynamicSharedMemorySize, EDGE_SMEM);
    cudaFuncSetAttribute(gemm_mma, cudaFuncAttributeMaxDynamicSharedMemorySize, GEMM_SMEM);

    dim3 tb(32, 8);

    init_kernel<<<(N_NODES * HID + 255) / 256, 256>>>(coord);
    deg_kernel<<<(N_EDGES + 255) / 256, 256>>>(row);
    emb_in_kernel<<<(N_NODES * HID + 255) / 256, 256>>>(x, emb_in_w, emb_in_b);

    for (int l = 0; l < N_LAYERS; l++) {
        const float* W1 = edge_w1 + l * 258 * HID;
        // A = h@W1a + b1 ; B = h@W1b
        wtrans_kernel<<<16, tb>>>(W1, pWtA);
        gemm_mma<<<GRID_G, 256, GEMM_SMEM>>>(ph, pWtA, edge_b1 + l * HID, pA, GM_BIAS);
        wtrans_kernel<<<16, tb>>>(W1 + 128 * HID, pWtA);
        gemm_mma<<<GRID_G, 256, GEMM_SMEM>>>(ph, pWtA, nullptr, pB, 0);
        // fused edge MLP
        wtrans_kernel<<<16, tb>>>(edge_w2 + l * HID * HID, pWtA);
        wtrans_kernel<<<16, tb>>>(coord_w1 + l * HID * HID, pWtB);
        edge_mma<<<GRID_E, 256, EDGE_SMEM>>>(row, col, ea,
            pWtA, edge_b2 + l * HID, pWtB, coord_b1 + l * HID, coord_w2 + l * HID,
            W1 + 256 * HID, W1 + 257 * HID);
        coord_kernel<<<(N_NODES + 255) / 256, 256>>>();
        // node update
        wtrans_kernel<<<16, tb>>>(node_w1 + l * 256 * HID, pWtA);
        gemm_mma<<<GRID_G, 256, GEMM_SMEM>>>(ph, pWtA, node_b1 + l * HID, pT, GM_BIAS);
        wtrans_kernel<<<16, tb>>>(node_w1 + l * 256 * HID + 128 * HID, pWtA);
        gemm_mma<<<GRID_G, 256, GEMM_SMEM>>>(pmagg, pWtA, nullptr, pT,
                                             GM_ACC | GM_SILU | GM_CLEARX);
        wtrans_kernel<<<16, tb>>>(node_w2 + l * HID * HID, pWtA);
        gemm_mma<<<GRID_G, 256, GEMM_SMEM>>>(pT, pWtA, node_b2 + l * HID, ph, GM_BIAS | GM_ACC);
    }

    wtrans_kernel<<<16, tb>>>(emb_out_w, pWtA);
    gemm_mma<<<GRID_G, 256, GEMM_SMEM>>>(ph, pWtA, emb_out_b, pA, GM_BIAS);
    pool_kernel<<<(N_NODES + 511) / 512, 128>>>(batch);
    fc_kernel<<<N_GRAPHS, 256>>>(fc_w, fc_b, out);
}